// round 11
// baseline (speedup 1.0000x reference)
#include <cuda_runtime.h>
#include <math.h>

#define NA   768
#define FDIM 128
#define NRBF 32
#define MAXNBR 192

// Physics constants (match reference exactly)
#define CUT2f   25.0f
#define GAMf    40.96f                       /* (32/5)^2 */
#define CSPf    (5.0f/31.0f)                 /* RBF center spacing */
#define KBf     8.617330337217213e-05f
#define KTf     (300.0f*KBf)
#define Q0f     (2.0f*(float)(NA*3)*KTf*400.0f)
#define QCf     (2.0f*KTf*400.0f)
#define TARGETf (0.5f*(float)(NA*3)*KTf)

// Scratch (static __device__ arrays: allocation-free, graph-safe)
__device__ int      g_nbr[NA*MAXNBR];
__device__ int      g_cnt[NA];
__device__ float    g_h  [NA*FDIM];
__device__ float    g_W3T[FDIM*FDIM];
__device__ float    g_gm [NA*FDIM];          // dE/dm per atom
__device__ float    g_gq [NA*3];             // dE/dq accumulator
__device__ unsigned g_relu[NA*MAXNBR*4];     // relu(z) mask bits per (pair, feature)

// group-scoped barrier: 128 threads, ids 1..2
__device__ __forceinline__ void barg(int id) {
    asm volatile("bar.sync %0, %1;" :: "r"(id), "r"(128) : "memory");
}

// ---------------------------------------------------------------------------
// K0: gather h = embed[atomic_numbers], transpose W3
__global__ void k_prep(const float* __restrict__ embed, const int* __restrict__ zat,
                       const float* __restrict__ W3) {
    int b = blockIdx.x, t = threadIdx.x;
    g_h[b*FDIM + t] = embed[zat[b]*FDIM + t];
    if (b < FDIM) g_W3T[b*FDIM + t] = W3[t*FDIM + b];
}

// ---------------------------------------------------------------------------
// K1: cutoff neighbor list (block per atom, q cached in smem) + zero forces
__global__ void k_nbr(const float* __restrict__ q) {
    __shared__ float sq[NA*3];
    __shared__ int cnt;
    int i = blockIdx.x, t = threadIdx.x;
    if (t == 0) cnt = 0;
    if (t < 3)  g_gq[i*3 + t] = 0.0f;
    for (int idx = t; idx < NA*3; idx += 256) sq[idx] = q[idx];
    __syncthreads();
    float qx = sq[3*i], qy = sq[3*i+1], qz = sq[3*i+2];
    for (int j = t; j < NA; j += 256) {
        if (j == i) continue;
        float dx = qx - sq[3*j], dy = qy - sq[3*j+1], dz = qz - sq[3*j+2];
        float d2 = dx*dx + dy*dy + dz*dz;
        if (d2 < CUT2f) {
            int p = atomicAdd(&cnt, 1);
            if (p < MAXNBR) g_nbr[i*MAXNBR + p] = j;
        }
    }
    __syncthreads();
    if (t == 0) g_cnt[i] = (cnt < MAXNBR) ? cnt : MAXNBR;
}

// ---------------------------------------------------------------------------
// K2: forward. Block = 256 = 2 groups of 128; groups split the f' REDUCTION.
// Thread (g,lt) holds W2[g*64+e, lt] (e<64) in registers: zero smem W2 traffic.
// Per iter: 4 neighbors; group g owns neighbors {2g, 2g+1} for z/finalize.
__global__ void __launch_bounds__(256, 2)
k_fwd(const float* __restrict__ q,
      const float* __restrict__ W1, const float* __restrict__ b1,
      const float* __restrict__ W2, const float* __restrict__ b2,
      const float* __restrict__ W3, const float* __restrict__ w_out) {
    __shared__ float sA[4*FDIM];      // relu(z) per neighbor
    __shared__ float rbfg[4*NRBF];
    __shared__ float sFp[4*FDIM];     // cross-group filt partials
    __shared__ float sPart[256];

    int i = blockIdx.x, t = threadIdx.x;
    int g = t >> 7, lt = t & 127;
    int n0 = 2*g, n1 = 2*g + 1;       // own neighbors (slot within quad)

    // W2 slice in registers: wreg[r] = W2[g*64+4r+e][lt], e=0..3 (coalesced loads)
    float4 wreg[16];
    #pragma unroll
    for (int r = 0; r < 16; r++) {
        int f0 = g*64 + 4*r;
        wreg[r].x = W2[(f0+0)*FDIM + lt];
        wreg[r].y = W2[(f0+1)*FDIM + lt];
        wreg[r].z = W2[(f0+2)*FDIM + lt];
        wreg[r].w = W2[(f0+3)*FDIM + lt];
    }

    float qx = q[3*i], qy = q[3*i+1], qz = q[3*i+2];
    float b1t = b1[lt], b2t = b2[lt];
    float m = 0.0f;
    int cnt = g_cnt[i];

    for (int base = 0; base < cnt; base += 4) {
        int jv[4]; bool val[4];
        #pragma unroll
        for (int n = 0; n < 4; n++) {
            int jn = base + n;
            val[n] = jn < cnt;
            jv[n]  = val[n] ? g_nbr[i*MAXNBR + jn] : i;
        }
        // rbf for own 2 neighbors (threads lt<64: nl=lt>>5, k=lt&31)
        if (lt < 64) {
            int nl = lt >> 5, k = lt & 31;
            int n = 2*g + nl, j = jv[n];
            float dx = qx - q[3*j], dy = qy - q[3*j+1], dz = qz - q[3*j+2];
            float d = val[n] ? sqrtf(dx*dx + dy*dy + dz*dz) : 1.0f;
            float u = d - (float)k * CSPf;
            rbfg[n*NRBF + k] = __expf(-GAMf * u * u);
        }
        __syncthreads();                                      // S1
        // z for own 2 neighbors; store relu + mask bits
        float z0 = b1t, z1 = b1t;
        #pragma unroll
        for (int k4 = 0; k4 < NRBF; k4 += 4) {
            float4 r0 = *(const float4*)&rbfg[n0*NRBF + k4];
            float4 r1 = *(const float4*)&rbfg[n1*NRBF + k4];
            #pragma unroll
            for (int e = 0; e < 4; e++) {
                float w = W1[(k4+e)*FDIM + lt];
                z0 = fmaf((&r0.x)[e], w, z0);
                z1 = fmaf((&r1.x)[e], w, z1);
            }
        }
        sA[n0*FDIM + lt] = fmaxf(z0, 0.0f);
        sA[n1*FDIM + lt] = fmaxf(z1, 0.0f);
        unsigned mk0 = __ballot_sync(0xffffffffu, z0 > 0.0f);
        unsigned mk1 = __ballot_sync(0xffffffffu, z1 > 0.0f);
        if ((lt & 31) == 0) {
            if (val[n0]) g_relu[(i*MAXNBR + base + n0)*4 + (lt>>5)] = mk0;
            if (val[n1]) g_relu[(i*MAXNBR + base + n1)*4 + (lt>>5)] = mk1;
        }
        __syncthreads();                                      // S2
        // filt partials over own f'-half for ALL 4 neighbors (W2 in regs)
        float f0 = 0.f, f1 = 0.f, f2 = 0.f, f3 = 0.f;
        #pragma unroll
        for (int r = 0; r < 16; r++) {
            float4 w = wreg[r];
            int fb = g*64 + 4*r;
            float4 a0 = *(const float4*)&sA[0*FDIM + fb];
            float4 a1 = *(const float4*)&sA[1*FDIM + fb];
            float4 a2 = *(const float4*)&sA[2*FDIM + fb];
            float4 a3 = *(const float4*)&sA[3*FDIM + fb];
            f0 = fmaf(a0.x,w.x,f0); f0 = fmaf(a0.y,w.y,f0);
            f0 = fmaf(a0.z,w.z,f0); f0 = fmaf(a0.w,w.w,f0);
            f1 = fmaf(a1.x,w.x,f1); f1 = fmaf(a1.y,w.y,f1);
            f1 = fmaf(a1.z,w.z,f1); f1 = fmaf(a1.w,w.w,f1);
            f2 = fmaf(a2.x,w.x,f2); f2 = fmaf(a2.y,w.y,f2);
            f2 = fmaf(a2.z,w.z,f2); f2 = fmaf(a2.w,w.w,f2);
            f3 = fmaf(a3.x,w.x,f3); f3 = fmaf(a3.y,w.y,f3);
            f3 = fmaf(a3.z,w.z,f3); f3 = fmaf(a3.w,w.w,f3);
        }
        // hand partials for the other group's neighbors to smem
        if (g == 0) { sFp[2*FDIM + lt] = f2; sFp[3*FDIM + lt] = f3; }
        else        { sFp[0*FDIM + lt] = f0; sFp[1*FDIM + lt] = f1; }
        __syncthreads();                                      // S3
        float own0 = (g == 0) ? f0 : f2;
        float own1 = (g == 0) ? f1 : f3;
        float filt0 = b2t + own0 + sFp[n0*FDIM + lt];
        float filt1 = b2t + own1 + sFp[n1*FDIM + lt];
        if (val[n0]) m = fmaf(filt0, g_h[jv[n0]*FDIM + lt], m);
        if (val[n1]) m = fmaf(filt1, g_h[jv[n1]*FDIM + lt], m);
    }

    // combine group partials, then head: a = m@W3 ; gm = W3 @ (w_out * 1[a>0])
    __syncthreads();
    sPart[t] = m;
    __syncthreads();
    if (g == 0) {
        float mt = sPart[lt] + sPart[128 + lt];
        float* sM = sA;
        float* sB = sA + FDIM;
        sM[lt] = mt;
        barg(1);
        float a = 0.0f;
        #pragma unroll 8
        for (int f = 0; f < FDIM; f++) a = fmaf(sM[f], W3[f*FDIM + lt], a);
        sB[lt] = (a > 0.0f) ? w_out[lt] : 0.0f;
        barg(1);
        float gm = 0.0f;
        #pragma unroll 8
        for (int f = 0; f < FDIM; f++) gm = fmaf(sB[f], g_W3T[f*FDIM + lt], gm);
        g_gm[i*FDIM + lt] = gm;
    }
}

// ---------------------------------------------------------------------------
// K3: backward. Thread (g,lt) holds W2[lt, g*64+e] in registers (contiguous).
// relu mask read from g_relu (no z recompute). Groups split f in gz reduction.
__global__ void __launch_bounds__(256, 2)
k_bwd(const float* __restrict__ q,
      const float* __restrict__ W1,
      const float* __restrict__ W2) {
    __shared__ float crbfg[4*NRBF];
    __shared__ float sD[16];          // {dx,dy,dz,d} per neighbor slot
    __shared__ float sgf[4*FDIM];
    __shared__ float sGz[4*FDIM];
    __shared__ float sRed[32];        // [n(4)][warp-in-group(4)] x 2 groups

    int i = blockIdx.x, t = threadIdx.x;
    int g = t >> 7, lt = t & 127, warp = lt >> 5, lane = t & 31;
    int n0 = 2*g, n1 = 2*g + 1;

    float4 wreg[16];                  // W2[lt, g*64+4r+e]
    #pragma unroll
    for (int r = 0; r < 16; r++)
        wreg[r] = *(const float4*)&W2[lt*FDIM + g*64 + 4*r];

    float qx = q[3*i], qy = q[3*i+1], qz = q[3*i+2];
    float gmf = g_gm[i*FDIM + lt];
    int cnt = g_cnt[i];

    for (int base = 0; base < cnt; base += 4) {
        int jv[4]; bool val[4];
        #pragma unroll
        for (int n = 0; n < 4; n++) {
            int jn = base + n;
            val[n] = jn < cnt;
            jv[n]  = val[n] ? g_nbr[i*MAXNBR + jn] : i;
        }
        // crbf + geometry for own 2 neighbors
        if (lt < 64) {
            int nl = lt >> 5, k = lt & 31;
            int n = 2*g + nl, j = jv[n];
            float dx = qx - q[3*j], dy = qy - q[3*j+1], dz = qz - q[3*j+2];
            float d = val[n] ? sqrtf(dx*dx + dy*dy + dz*dz) : 1.0f;
            float u = d - (float)k * CSPf;
            float e = __expf(-GAMf * u * u);
            crbfg[n*NRBF + k] = -2.0f * GAMf * u * e;
            if (k == 0) { sD[n*4+0]=dx; sD[n*4+1]=dy; sD[n*4+2]=dz; sD[n*4+3]=d; }
        }
        // sgf for own 2 neighbors (needed by both groups)
        sgf[n0*FDIM + lt] = val[n0] ? gmf * g_h[jv[n0]*FDIM + lt] : 0.0f;
        sgf[n1*FDIM + lt] = val[n1] ? gmf * g_h[jv[n1]*FDIM + lt] : 0.0f;
        __syncthreads();                                      // S1
        // gz partials over own f-half for ALL 4 neighbors (W2 in regs)
        float p0 = 0.f, p1 = 0.f, p2 = 0.f, p3 = 0.f;
        #pragma unroll
        for (int r = 0; r < 16; r++) {
            float4 w = wreg[r];
            int fb = g*64 + 4*r;
            float4 a0 = *(const float4*)&sgf[0*FDIM + fb];
            float4 a1 = *(const float4*)&sgf[1*FDIM + fb];
            float4 a2 = *(const float4*)&sgf[2*FDIM + fb];
            float4 a3 = *(const float4*)&sgf[3*FDIM + fb];
            p0 = fmaf(a0.x,w.x,p0); p0 = fmaf(a0.y,w.y,p0);
            p0 = fmaf(a0.z,w.z,p0); p0 = fmaf(a0.w,w.w,p0);
            p1 = fmaf(a1.x,w.x,p1); p1 = fmaf(a1.y,w.y,p1);
            p1 = fmaf(a1.z,w.z,p1); p1 = fmaf(a1.w,w.w,p1);
            p2 = fmaf(a2.x,w.x,p2); p2 = fmaf(a2.y,w.y,p2);
            p2 = fmaf(a2.z,w.z,p2); p2 = fmaf(a2.w,w.w,p2);
            p3 = fmaf(a3.x,w.x,p3); p3 = fmaf(a3.y,w.y,p3);
            p3 = fmaf(a3.z,w.z,p3); p3 = fmaf(a3.w,w.w,p3);
        }
        if (g == 0) { sGz[2*FDIM + lt] = p2; sGz[3*FDIM + lt] = p3; }
        else        { sGz[0*FDIM + lt] = p0; sGz[1*FDIM + lt] = p1; }
        __syncthreads();                                      // S2
        // finalize gz for own 2 neighbors with stored relu mask
        float gz0 = ((g == 0) ? p0 : p2) + sGz[n0*FDIM + lt];
        float gz1 = ((g == 0) ? p1 : p3) + sGz[n1*FDIM + lt];
        unsigned w0 = val[n0] ? g_relu[(i*MAXNBR + base + n0)*4 + warp] : 0u;
        unsigned w1 = val[n1] ? g_relu[(i*MAXNBR + base + n1)*4 + warp] : 0u;
        if (!((w0 >> (lt & 31)) & 1u)) gz0 = 0.0f;
        if (!((w1 >> (lt & 31)) & 1u)) gz1 = 0.0f;
        // c = (W1^T @ crbf)_lt for own 2 neighbors
        float c0 = 0.f, c1 = 0.f;
        #pragma unroll
        for (int k4 = 0; k4 < NRBF; k4 += 4) {
            float4 r0 = *(const float4*)&crbfg[n0*NRBF + k4];
            float4 r1 = *(const float4*)&crbfg[n1*NRBF + k4];
            #pragma unroll
            for (int e = 0; e < 4; e++) {
                float w = W1[(k4+e)*FDIM + lt];
                c0 = fmaf((&r0.x)[e], w, c0);
                c1 = fmaf((&r1.x)[e], w, c1);
            }
        }
        float q0 = gz0 * c0, q1 = gz1 * c1;
        #pragma unroll
        for (int off = 16; off > 0; off >>= 1) {
            q0 += __shfl_down_sync(0xffffffffu, q0, off);
            q1 += __shfl_down_sync(0xffffffffu, q1, off);
        }
        if (lane == 0) { sRed[n0*4 + warp] = q0; sRed[n1*4 + warp] = q1; }
        // cache geometry in regs BEFORE the barrier (sD is rewritten next iter)
        float ddx = 0.f, ddy = 0.f, ddz = 0.f, dd = 1.f;
        int nf = 2*g + lt;            // finalizer's neighbor slot (lt<2)
        if (lt < 2) { ddx = sD[nf*4+0]; ddy = sD[nf*4+1]; ddz = sD[nf*4+2]; dd = sD[nf*4+3]; }
        __syncthreads();                                      // S3
        if (lt < 2 && val[nf]) {
            float s = (sRed[nf*4+0] + sRed[nf*4+1] + sRed[nf*4+2] + sRed[nf*4+3]) / dd;
            float gx = s*ddx, gy = s*ddy, gzc = s*ddz;
            atomicAdd(&g_gq[3*i+0],  gx);
            atomicAdd(&g_gq[3*i+1],  gy);
            atomicAdd(&g_gq[3*i+2],  gzc);
            int j = jv[nf];
            atomicAdd(&g_gq[3*j+0], -gx);
            atomicAdd(&g_gq[3*j+1], -gy);
            atomicAdd(&g_gq[3*j+2], -gzc);
        }
    }
}

// ---------------------------------------------------------------------------
// K4: KE reduction + dvdt + v passthrough + Nose-Hoover chain RHS
__global__ void k_fin(const float* __restrict__ v, const float* __restrict__ mass,
                      const float* __restrict__ p_eta, float* __restrict__ out) {
    __shared__ float red[256];
    int t = threadIdx.x;
    float ke = 0.0f;
    for (int n = t; n < NA; n += 256) {
        float mn = mass[n];
        float v0 = v[3*n], v1 = v[3*n+1], v2 = v[3*n+2];
        ke += mn * (v0*v0 + v1*v1 + v2*v2);
    }
    red[t] = ke;
    __syncthreads();
    for (int off = 128; off > 0; off >>= 1) {
        if (t < off) red[t] += red[t + off];
        __syncthreads();
    }
    float pe0 = p_eta[0];
    for (int idx = t; idx < NA*3; idx += 256) {
        int n = idx / 3;
        float mn = mass[n], vv = v[idx];
        out[idx]        = (-g_gq[idx] - pe0 * mn * vv / Q0f) / mn;
        out[NA*3 + idx] = vv;
    }
    if (t == 0) {
        float s_ke = 0.5f * red[0];
        float pe1 = p_eta[1], pe2 = p_eta[2], pe3 = p_eta[3];
        out[2*NA*3 + 0] = 2.0f*(s_ke - TARGETf) - pe0*pe1/QCf;
        out[2*NA*3 + 1] = pe0*pe0/Q0f - KTf - pe1*pe2/QCf;
        out[2*NA*3 + 2] = pe1*pe1/QCf - KTf - pe2*pe3/QCf;
        out[2*NA*3 + 3] = pe2*pe2/QCf - KTf;
    }
}

// ---------------------------------------------------------------------------
extern "C" void kernel_launch(void* const* d_in, const int* in_sizes, int n_in,
                              void* d_out, int out_size) {
    const float* v     = (const float*)d_in[0];
    const float* q     = (const float*)d_in[1];
    const float* p_eta = (const float*)d_in[2];
    const float* mass  = (const float*)d_in[3];
    const float* embed = (const float*)d_in[4];
    const float* W1    = (const float*)d_in[5];
    const float* b1    = (const float*)d_in[6];
    const float* W2    = (const float*)d_in[7];
    const float* b2    = (const float*)d_in[8];
    const float* W3    = (const float*)d_in[9];
    const float* w_out = (const float*)d_in[10];
    const int*   zat   = (const int*)d_in[11];
    float* out = (float*)d_out;
    (void)in_sizes; (void)n_in; (void)out_size;

    k_prep<<<NA, FDIM>>>(embed, zat, W3);
    k_nbr <<<NA, 256 >>>(q);
    k_fwd <<<NA, 256 >>>(q, W1, b1, W2, b2, W3, w_out);
    k_bwd <<<NA, 256 >>>(q, W1, W2);
    k_fin <<<1,  256 >>>(v, mass, p_eta, out);
}

// round 12
// speedup vs baseline: 1.0881x; 1.0881x over previous
#include <cuda_runtime.h>
#include <math.h>

#define NA   768
#define FDIM 128
#define NRBF 32
#define MAXNBR 192
#define W2PAD 132            /* row stride: 132*4B = 528B, 16B-aligned; mod 32 banks = 4 */

// Physics constants (match reference exactly)
#define CUT2f   25.0f
#define GAMf    40.96f                       /* (32/5)^2 */
#define CSPf    (5.0f/31.0f)                 /* RBF center spacing */
#define KBf     8.617330337217213e-05f
#define KTf     (300.0f*KBf)
#define Q0f     (2.0f*(float)(NA*3)*KTf*400.0f)
#define QCf     (2.0f*KTf*400.0f)
#define TARGETf (0.5f*(float)(NA*3)*KTf)

typedef unsigned long long ull;

// packed fp32x2 helpers (Blackwell FFMA2 — PTX-only, ptxas won't auto-fuse)
__device__ __forceinline__ void fma2(ull& d, ull a, ull b) {
    asm("fma.rn.f32x2 %0, %1, %2, %0;" : "+l"(d) : "l"(a), "l"(b));
}
__device__ __forceinline__ ull pk2(float lo, float hi) {
    ull r; asm("mov.b64 %0, {%1, %2};" : "=l"(r) : "f"(lo), "f"(hi)); return r;
}
__device__ __forceinline__ float hadd2(ull v) {
    float lo, hi; asm("mov.b64 {%0, %1}, %2;" : "=f"(lo), "=f"(hi) : "l"(v));
    return lo + hi;
}

// Scratch (static __device__ arrays: allocation-free, graph-safe)
__device__ int      g_nbr[NA*MAXNBR];
__device__ int      g_cnt[NA];
__device__ float    g_h  [NA*FDIM];
__device__ float    g_W3T[FDIM*FDIM];
__device__ float    g_gm [NA*FDIM];          // dE/dm per atom
__device__ float    g_gq [NA*3];             // dE/dq accumulator
__device__ unsigned g_relu[NA*MAXNBR*4];     // relu(z) mask bits per (pair, warp)

// group-scoped barrier: 128 threads, ids 1..2
__device__ __forceinline__ void barg(int id) {
    asm volatile("bar.sync %0, %1;" :: "r"(id), "r"(128) : "memory");
}

// ---------------------------------------------------------------------------
// K0: gather h = embed[atomic_numbers], transpose W3
__global__ void k_prep(const float* __restrict__ embed, const int* __restrict__ zat,
                       const float* __restrict__ W3) {
    int b = blockIdx.x, t = threadIdx.x;
    g_h[b*FDIM + t] = embed[zat[b]*FDIM + t];
    if (b < FDIM) g_W3T[b*FDIM + t] = W3[t*FDIM + b];
}

// ---------------------------------------------------------------------------
// K1: cutoff neighbor list (block per atom, q cached in smem) + zero forces
__global__ void k_nbr(const float* __restrict__ q) {
    __shared__ float sq[NA*3];
    __shared__ int cnt;
    int i = blockIdx.x, t = threadIdx.x;
    if (t == 0) cnt = 0;
    if (t < 3)  g_gq[i*3 + t] = 0.0f;
    for (int idx = t; idx < NA*3; idx += 256) sq[idx] = q[idx];
    __syncthreads();
    float qx = sq[3*i], qy = sq[3*i+1], qz = sq[3*i+2];
    for (int j = t; j < NA; j += 256) {
        if (j == i) continue;
        float dx = qx - sq[3*j], dy = qy - sq[3*j+1], dz = qz - sq[3*j+2];
        float d2 = dx*dx + dy*dy + dz*dz;
        if (d2 < CUT2f) {
            int p = atomicAdd(&cnt, 1);
            if (p < MAXNBR) g_nbr[i*MAXNBR + p] = j;
        }
    }
    __syncthreads();
    if (t == 0) g_cnt[i] = (cnt < MAXNBR) ? cnt : MAXNBR;
}

// ---------------------------------------------------------------------------
// K2: forward messages m_i + fused head dE/dm_i.
// Block = 256 = 2 independent groups of 128; 4 neighbors per group-iter.
// Big reductions run on fma.rn.f32x2 (adjacent-f lanes packed).
#define FWD_SMEM_FLOATS (FDIM*W2PAD + 2*640 + 256)
__global__ void __launch_bounds__(256, 3)
k_fwd(const float* __restrict__ q,
      const float* __restrict__ W1, const float* __restrict__ b1,
      const float* __restrict__ W2, const float* __restrict__ b2,
      const float* __restrict__ W3, const float* __restrict__ w_out) {
    extern __shared__ float sm[];
    float* sW2T = sm;                                 // 128*W2PAD (W2 transposed)
    int i = blockIdx.x, t = threadIdx.x;
    int g = t >> 7, lt = t & 127;
    float* grp   = sm + FDIM*W2PAD + g*640;
    float* rbf   = grp;                               // 4*32
    float* sA    = grp + 128;                         // 4*128
    float* sPart = sm + FDIM*W2PAD + 1280;            // 256

    for (int idx = t; idx < FDIM*FDIM; idx += 256)
        sW2T[(idx & 127)*W2PAD + (idx >> 7)] = W2[idx];

    float qx = q[3*i], qy = q[3*i+1], qz = q[3*i+2];
    float b1t = b1[lt], b2t = b2[lt];
    float m = 0.0f;
    int cnt = g_cnt[i];
    __syncthreads();

    for (int base = g*4; base < cnt; base += 8) {
        int jv[4]; bool val[4];
        #pragma unroll
        for (int n = 0; n < 4; n++) {
            int jn = base + n;
            val[n] = jn < cnt;
            jv[n]  = val[n] ? g_nbr[i*MAXNBR + jn] : i;
        }
        barg(g+1);
        {   // 128 threads: n = lt>>5 neighbor, k = lt&31 rbf index
            int n = lt >> 5, k = lt & 31;
            int j = jv[n];
            float dx = qx - q[3*j], dy = qy - q[3*j+1], dz = qz - q[3*j+2];
            float d = val[n] ? sqrtf(dx*dx + dy*dy + dz*dz) : 1.0f;
            float u = d - (float)k * CSPf;
            rbf[lt] = __expf(-GAMf * u * u);
        }
        barg(g+1);
        // z_n = b1 + rbf_n @ W1  (f32x2 over k-pairs, W1 scalars packed)
        ull Z0 = 0, Z1 = 0, Z2 = 0, Z3 = 0;
        #pragma unroll
        for (int k4 = 0; k4 < NRBF; k4 += 4) {
            float w0 = W1[(k4+0)*FDIM + lt], w1 = W1[(k4+1)*FDIM + lt];
            float w2 = W1[(k4+2)*FDIM + lt], w3 = W1[(k4+3)*FDIM + lt];
            ull wp0 = pk2(w0, w1), wp1 = pk2(w2, w3);
            ulonglong2 r0 = *(const ulonglong2*)&rbf[0*32+k4];
            ulonglong2 r1 = *(const ulonglong2*)&rbf[1*32+k4];
            ulonglong2 r2 = *(const ulonglong2*)&rbf[2*32+k4];
            ulonglong2 r3 = *(const ulonglong2*)&rbf[3*32+k4];
            fma2(Z0, r0.x, wp0); fma2(Z0, r0.y, wp1);
            fma2(Z1, r1.x, wp0); fma2(Z1, r1.y, wp1);
            fma2(Z2, r2.x, wp0); fma2(Z2, r2.y, wp1);
            fma2(Z3, r3.x, wp0); fma2(Z3, r3.y, wp1);
        }
        float z0 = b1t + hadd2(Z0), z1 = b1t + hadd2(Z1);
        float z2 = b1t + hadd2(Z2), z3 = b1t + hadd2(Z3);
        sA[0*128+lt] = fmaxf(z0, 0.0f);
        sA[1*128+lt] = fmaxf(z1, 0.0f);
        sA[2*128+lt] = fmaxf(z2, 0.0f);
        sA[3*128+lt] = fmaxf(z3, 0.0f);
        // relu mask bits for bwd (word = warp index, bit = lane)
        unsigned mk0 = __ballot_sync(0xffffffffu, z0 > 0.0f);
        unsigned mk1 = __ballot_sync(0xffffffffu, z1 > 0.0f);
        unsigned mk2 = __ballot_sync(0xffffffffu, z2 > 0.0f);
        unsigned mk3 = __ballot_sync(0xffffffffu, z3 > 0.0f);
        if ((lt & 31) == 0) {
            int w = lt >> 5;
            if (val[0]) g_relu[(i*MAXNBR + base + 0)*4 + w] = mk0;
            if (val[1]) g_relu[(i*MAXNBR + base + 1)*4 + w] = mk1;
            if (val[2]) g_relu[(i*MAXNBR + base + 2)*4 + w] = mk2;
            if (val[3]) g_relu[(i*MAXNBR + base + 3)*4 + w] = mk3;
        }
        barg(g+1);
        // filt_n[lt] = b2 + sum_f A_n[f] * W2[f,lt]  (f32x2 over f-pairs)
        ull F0 = 0, F1 = 0, F2 = 0, F3 = 0;
        #pragma unroll 8
        for (int f4 = 0; f4 < FDIM; f4 += 4) {
            ulonglong2 w  = *(const ulonglong2*)&sW2T[lt*W2PAD + f4];
            ulonglong2 a0 = *(const ulonglong2*)&sA[0*128+f4];
            ulonglong2 a1 = *(const ulonglong2*)&sA[1*128+f4];
            ulonglong2 a2 = *(const ulonglong2*)&sA[2*128+f4];
            ulonglong2 a3 = *(const ulonglong2*)&sA[3*128+f4];
            fma2(F0, a0.x, w.x); fma2(F0, a0.y, w.y);
            fma2(F1, a1.x, w.x); fma2(F1, a1.y, w.y);
            fma2(F2, a2.x, w.x); fma2(F2, a2.y, w.y);
            fma2(F3, a3.x, w.x); fma2(F3, a3.y, w.y);
        }
        float f0 = b2t + hadd2(F0), f1 = b2t + hadd2(F1);
        float f2 = b2t + hadd2(F2), f3 = b2t + hadd2(F3);
        if (val[0]) m = fmaf(f0, g_h[jv[0]*FDIM + lt], m);
        if (val[1]) m = fmaf(f1, g_h[jv[1]*FDIM + lt], m);
        if (val[2]) m = fmaf(f2, g_h[jv[2]*FDIM + lt], m);
        if (val[3]) m = fmaf(f3, g_h[jv[3]*FDIM + lt], m);
    }

    // combine group partials, then head: a = m@W3 ; gm = W3 @ (w_out * 1[a>0])
    __syncthreads();
    sPart[t] = m;
    __syncthreads();
    if (g == 0) {
        float mt = sPart[lt] + sPart[128 + lt];
        float* sM = sA;           // group-0 scratch reuse
        float* sB = sA + 128;
        sM[lt] = mt;
        barg(1);
        float a = 0.0f;
        #pragma unroll 8
        for (int f = 0; f < FDIM; f++) a = fmaf(sM[f], W3[f*FDIM + lt], a);
        sB[lt] = (a > 0.0f) ? w_out[lt] : 0.0f;
        barg(1);
        float gm = 0.0f;
        #pragma unroll 8
        for (int f = 0; f < FDIM; f++) gm = fmaf(sB[f], g_W3T[f*FDIM + lt], gm);
        g_gm[i*FDIM + lt] = gm;
    }
}

// ---------------------------------------------------------------------------
// K3: backward per pair -> dE/dq scatter.
// relu mask from g_relu (no z recompute, no rbf buffer). gz + c loops on f32x2.
#define BWD_SMEM_FLOATS (FDIM*W2PAD + 2*672)
__global__ void __launch_bounds__(256, 3)
k_bwd(const float* __restrict__ q,
      const float* __restrict__ W1,
      const float* __restrict__ W2) {
    extern __shared__ float sm[];
    float* sW2 = sm;              // W2 row-major as-is: gz needs rows of W2
    int i = blockIdx.x, t = threadIdx.x;
    int g = t >> 7, lt = t & 127, warp = lt >> 5, lane = t & 31;
    float* grp  = sm + FDIM*W2PAD + g*672;
    float* crbf = grp;            // 4*32
    float* sgf  = grp + 128;      // 4*128
    float* sRed = grp + 640;      // 16
    float* sD   = grp + 656;      // 16: {dx,dy,dz,d} per neighbor lane

    for (int idx = t; idx < FDIM*FDIM; idx += 256)
        sW2[(idx >> 7)*W2PAD + (idx & 127)] = W2[idx];

    float qx = q[3*i], qy = q[3*i+1], qz = q[3*i+2];
    float gmf = g_gm[i*FDIM + lt];
    int cnt = g_cnt[i];
    __syncthreads();

    for (int base = g*4; base < cnt; base += 8) {
        int jv[4]; bool val[4];
        #pragma unroll
        for (int n = 0; n < 4; n++) {
            int jn = base + n;
            val[n] = jn < cnt;
            jv[n]  = val[n] ? g_nbr[i*MAXNBR + jn] : i;
        }
        barg(g+1);
        {
            int n = lt >> 5, k = lt & 31;
            int j = jv[n];
            float dx = qx - q[3*j], dy = qy - q[3*j+1], dz = qz - q[3*j+2];
            float d = val[n] ? sqrtf(dx*dx + dy*dy + dz*dz) : 1.0f;
            float u = d - (float)k * CSPf;
            float e = __expf(-GAMf * u * u);
            crbf[lt] = -2.0f * GAMf * u * e;
            if (k == 0) { sD[n*4+0]=dx; sD[n*4+1]=dy; sD[n*4+2]=dz; sD[n*4+3]=d; }
        }
        #pragma unroll
        for (int n = 0; n < 4; n++)
            sgf[n*128 + lt] = val[n] ? gmf * g_h[jv[n]*FDIM + lt] : 0.0f;
        barg(g+1);
        // c_n = (W1^T @ crbf_n)_lt  (f32x2 over k-pairs)
        ull C0 = 0, C1 = 0, C2 = 0, C3 = 0;
        #pragma unroll
        for (int k4 = 0; k4 < NRBF; k4 += 4) {
            float w0 = W1[(k4+0)*FDIM + lt], w1 = W1[(k4+1)*FDIM + lt];
            float w2 = W1[(k4+2)*FDIM + lt], w3 = W1[(k4+3)*FDIM + lt];
            ull wp0 = pk2(w0, w1), wp1 = pk2(w2, w3);
            ulonglong2 r0 = *(const ulonglong2*)&crbf[0*32+k4];
            ulonglong2 r1 = *(const ulonglong2*)&crbf[1*32+k4];
            ulonglong2 r2 = *(const ulonglong2*)&crbf[2*32+k4];
            ulonglong2 r3 = *(const ulonglong2*)&crbf[3*32+k4];
            fma2(C0, r0.x, wp0); fma2(C0, r0.y, wp1);
            fma2(C1, r1.x, wp0); fma2(C1, r1.y, wp1);
            fma2(C2, r2.x, wp0); fma2(C2, r2.y, wp1);
            fma2(C3, r3.x, wp0); fma2(C3, r3.y, wp1);
        }
        // gz_n[lt] = sum_f gfilt_n[f] * W2[lt,f]  (f32x2 over f-pairs)
        ull G0 = 0, G1 = 0, G2 = 0, G3 = 0;
        #pragma unroll 8
        for (int f4 = 0; f4 < FDIM; f4 += 4) {
            ulonglong2 w  = *(const ulonglong2*)&sW2[lt*W2PAD + f4];
            ulonglong2 a0 = *(const ulonglong2*)&sgf[0*128+f4];
            ulonglong2 a1 = *(const ulonglong2*)&sgf[1*128+f4];
            ulonglong2 a2 = *(const ulonglong2*)&sgf[2*128+f4];
            ulonglong2 a3 = *(const ulonglong2*)&sgf[3*128+f4];
            fma2(G0, a0.x, w.x); fma2(G0, a0.y, w.y);
            fma2(G1, a1.x, w.x); fma2(G1, a1.y, w.y);
            fma2(G2, a2.x, w.x); fma2(G2, a2.y, w.y);
            fma2(G3, a3.x, w.x); fma2(G3, a3.y, w.y);
        }
        // relu masks stored by fwd (broadcast loads)
        unsigned m0 = val[0] ? g_relu[(i*MAXNBR + base + 0)*4 + warp] : 0u;
        unsigned m1 = val[1] ? g_relu[(i*MAXNBR + base + 1)*4 + warp] : 0u;
        unsigned m2 = val[2] ? g_relu[(i*MAXNBR + base + 2)*4 + warp] : 0u;
        unsigned m3 = val[3] ? g_relu[(i*MAXNBR + base + 3)*4 + warp] : 0u;
        float p0 = ((m0 >> lane) & 1u) ? hadd2(G0) * hadd2(C0) : 0.0f;
        float p1 = ((m1 >> lane) & 1u) ? hadd2(G1) * hadd2(C1) : 0.0f;
        float p2 = ((m2 >> lane) & 1u) ? hadd2(G2) * hadd2(C2) : 0.0f;
        float p3 = ((m3 >> lane) & 1u) ? hadd2(G3) * hadd2(C3) : 0.0f;
        #pragma unroll
        for (int off = 16; off > 0; off >>= 1) {
            p0 += __shfl_down_sync(0xffffffffu, p0, off);
            p1 += __shfl_down_sync(0xffffffffu, p1, off);
            p2 += __shfl_down_sync(0xffffffffu, p2, off);
            p3 += __shfl_down_sync(0xffffffffu, p3, off);
        }
        if (lane == 0) {
            sRed[0*4+warp] = p0; sRed[1*4+warp] = p1;
            sRed[2*4+warp] = p2; sRed[3*4+warp] = p3;
        }
        barg(g+1);
        if (lt < 4 && (base + lt) < cnt) {
            int n = lt;
            float s = (sRed[n*4+0] + sRed[n*4+1] + sRed[n*4+2] + sRed[n*4+3]) / sD[n*4+3];
            float gx = s*sD[n*4+0], gy = s*sD[n*4+1], gzc = s*sD[n*4+2];
            atomicAdd(&g_gq[3*i+0],  gx);
            atomicAdd(&g_gq[3*i+1],  gy);
            atomicAdd(&g_gq[3*i+2],  gzc);
            int j = jv[n];
            atomicAdd(&g_gq[3*j+0], -gx);
            atomicAdd(&g_gq[3*j+1], -gy);
            atomicAdd(&g_gq[3*j+2], -gzc);
        }
    }
}

// ---------------------------------------------------------------------------
// K4: KE reduction + dvdt + v passthrough + Nose-Hoover chain RHS
__global__ void k_fin(const float* __restrict__ v, const float* __restrict__ mass,
                      const float* __restrict__ p_eta, float* __restrict__ out) {
    __shared__ float red[256];
    int t = threadIdx.x;
    float ke = 0.0f;
    for (int n = t; n < NA; n += 256) {
        float mn = mass[n];
        float v0 = v[3*n], v1 = v[3*n+1], v2 = v[3*n+2];
        ke += mn * (v0*v0 + v1*v1 + v2*v2);
    }
    red[t] = ke;
    __syncthreads();
    for (int off = 128; off > 0; off >>= 1) {
        if (t < off) red[t] += red[t + off];
        __syncthreads();
    }
    float pe0 = p_eta[0];
    for (int idx = t; idx < NA*3; idx += 256) {
        int n = idx / 3;
        float mn = mass[n], vv = v[idx];
        out[idx]        = (-g_gq[idx] - pe0 * mn * vv / Q0f) / mn;
        out[NA*3 + idx] = vv;
    }
    if (t == 0) {
        float s_ke = 0.5f * red[0];
        float pe1 = p_eta[1], pe2 = p_eta[2], pe3 = p_eta[3];
        out[2*NA*3 + 0] = 2.0f*(s_ke - TARGETf) - pe0*pe1/QCf;
        out[2*NA*3 + 1] = pe0*pe0/Q0f - KTf - pe1*pe2/QCf;
        out[2*NA*3 + 2] = pe1*pe1/QCf - KTf - pe2*pe3/QCf;
        out[2*NA*3 + 3] = pe2*pe2/QCf - KTf;
    }
}

// ---------------------------------------------------------------------------
extern "C" void kernel_launch(void* const* d_in, const int* in_sizes, int n_in,
                              void* d_out, int out_size) {
    const float* v     = (const float*)d_in[0];
    const float* q     = (const float*)d_in[1];
    const float* p_eta = (const float*)d_in[2];
    const float* mass  = (const float*)d_in[3];
    const float* embed = (const float*)d_in[4];
    const float* W1    = (const float*)d_in[5];
    const float* b1    = (const float*)d_in[6];
    const float* W2    = (const float*)d_in[7];
    const float* b2    = (const float*)d_in[8];
    const float* W3    = (const float*)d_in[9];
    const float* w_out = (const float*)d_in[10];
    const int*   zat   = (const int*)d_in[11];
    float* out = (float*)d_out;
    (void)in_sizes; (void)n_in; (void)out_size;

    const int fwd_smem = FWD_SMEM_FLOATS * (int)sizeof(float);   // ~72 KB
    const int bwd_smem = BWD_SMEM_FLOATS * (int)sizeof(float);   // ~71 KB
    cudaFuncSetAttribute(k_fwd, cudaFuncAttributeMaxDynamicSharedMemorySize, fwd_smem);
    cudaFuncSetAttribute(k_bwd, cudaFuncAttributeMaxDynamicSharedMemorySize, bwd_smem);

    k_prep<<<NA, FDIM>>>(embed, zat, W3);
    k_nbr <<<NA, 256 >>>(q);
    k_fwd <<<NA, 256, fwd_smem>>>(q, W1, b1, W2, b2, W3, w_out);
    k_bwd <<<NA, 256, bwd_smem>>>(q, W1, W2);
    k_fin <<<1,  256 >>>(v, mass, p_eta, out);
}